// round 5
// baseline (speedup 1.0000x reference)
#include <cuda_runtime.h>
#include <cstdint>

// YoloLayer2: x (16, 3*85, 76, 76) f32 -> out (16, 3, 76, 76, 85) f32
// Persistent, double-buffered smem, TMA bulk-store writes.

#define NUM_B 16
#define NUM_A 3
#define DIM_H 76
#define DIM_W 76
#define HW (DIM_H * DIM_W)        // 5776
#define ATTR 85
#define TILE_P 64                 // pixels per tile
#define V4 (TILE_P / 4)           // 16 float4 per attr row
#define NTHREADS 256
#define ITEMS (ATTR * V4)         // 1360 float4 work items per tile
#define NITER 6                   // ceil(ITEMS / NTHREADS)
#define TILES_PER_BA 91           // ceil(5776/64), last tile has 16 pixels
#define TILES_TOTAL (NUM_B * NUM_A * TILES_PER_BA)   // 4368
#define NSM 148
#define CTAS_PER_SM 5
#define NBLOCKS (NSM * CTAS_PER_SM)   // 740 persistent blocks
#define TILE_FLOATS (TILE_P * ATTR)   // 5440

// sigmoid(v) = 0.5*tanh(v/2) + 0.5  -- single MUFU + FMA
__device__ __forceinline__ float fsigmoid(float v) {
    float t;
    asm("tanh.approx.f32 %0, %1;" : "=f"(t) : "f"(v * 0.5f));
    return fmaf(t, 0.5f, 0.5f);
}

__device__ __forceinline__ uint32_t smem_u32(const void* p) {
    uint32_t a;
    asm("{ .reg .u64 t; cvta.to.shared.u64 t, %1; cvt.u32.u64 %0, t; }"
        : "=r"(a) : "l"(p));
    return a;
}

__global__ __launch_bounds__(NTHREADS, CTAS_PER_SM)
void yolo_kernel(const float* __restrict__ x, float* __restrict__ out) {
    __shared__ float sm[2][TILE_FLOATS];   // 2 * 21760 B = 43520 B

    const int tid = threadIdx.x;
    const int G   = gridDim.x;

    // Per-thread static item decomposition: item i -> idx = tid + i*256
    int attr_i[NITER], pl_i[NITER];
    bool item_ok[NITER];
    #pragma unroll
    for (int i = 0; i < NITER; i++) {
        int idx = tid + i * NTHREADS;
        attr_i[i] = idx >> 4;
        pl_i[i]   = (idx & 15) << 2;
        item_ok[i] = (idx < ITEMS);
    }

    float4 v[NITER];

    // ---- prefetch first tile ----
    int t = blockIdx.x;
    {
        const int ba      = t / TILES_PER_BA;
        const int tile_in = t - ba * TILES_PER_BA;
        const int p0      = tile_in * TILE_P;
        const int nvalid  = min(TILE_P, HW - p0);
        const float* bin  = x + (size_t)ba * ATTR * HW + p0;
        #pragma unroll
        for (int i = 0; i < NITER; i++)
            if (item_ok[i] && pl_i[i] < nvalid)
                v[i] = *(const float4*)(bin + attr_i[i] * HW + pl_i[i]);
    }

    int buf = 0;
    for (; t < TILES_TOTAL; t += G, buf ^= 1) {
        const int ba      = t / TILES_PER_BA;
        const int tile_in = t - ba * TILES_PER_BA;
        const int a       = ba % NUM_A;
        const int p0      = tile_in * TILE_P;
        const int nvalid  = min(TILE_P, HW - p0);

        const float AW[3] = {10.0f, 13.0f, 16.0f};
        const float AH[3] = {13.0f, 16.0f, 30.0f};
        const float sw = AW[a] * (1.0f / 608.0f);
        const float sh = AH[a] * (1.0f / 608.0f);

        // next tile pointers (prefetch interleaved with compute)
        const int tn = t + G;
        const float* binn = nullptr;
        int nvalid_n = 0;
        if (tn < TILES_TOTAL) {
            const int ban = tn / TILES_PER_BA;
            const int tin = tn - ban * TILES_PER_BA;
            const int p0n = tin * TILE_P;
            nvalid_n = min(TILE_P, HW - p0n);
            binn = x + (size_t)ban * ATTR * HW + p0n;
        }

        float* __restrict__ smb = sm[buf];

        // ---- compute + transposed STS for tile t; prefetch tile t+G ----
        #pragma unroll
        for (int i = 0; i < NITER; i++) {
            const int attr = attr_i[i];
            const int pl   = pl_i[i];
            if (item_ok[i] && pl < nvalid) {
                float vv[4] = {v[i].x, v[i].y, v[i].z, v[i].w};
                float r[4];
                if (attr >= 4) {
                    #pragma unroll
                    for (int k = 0; k < 4; k++) r[k] = fsigmoid(vv[k]);
                } else if (attr == 0) {
                    #pragma unroll
                    for (int k = 0; k < 4; k++) {
                        const int p  = p0 + pl + k;
                        const int wi = p % DIM_W;
                        r[k] = ((float)wi + fsigmoid(vv[k])) * (1.0f / 76.0f);
                    }
                } else if (attr == 1) {
                    #pragma unroll
                    for (int k = 0; k < 4; k++) {
                        const int p  = p0 + pl + k;
                        const int hj = p / DIM_W;
                        r[k] = ((float)hj + fsigmoid(vv[k])) * (1.0f / 76.0f);
                    }
                } else if (attr == 2) {
                    #pragma unroll
                    for (int k = 0; k < 4; k++) r[k] = __expf(vv[k]) * sw;
                } else { // attr == 3
                    #pragma unroll
                    for (int k = 0; k < 4; k++) r[k] = __expf(vv[k]) * sh;
                }
                float* row = smb + pl * ATTR + attr;
                #pragma unroll
                for (int k = 0; k < 4; k++) row[k * ATTR] = r[k];
            }
            // prefetch same item for next tile
            if (binn && item_ok[i] && pl < nvalid_n)
                v[i] = *(const float4*)(binn + attr * HW + pl);
        }
        __syncthreads();   // all STS for this tile visible

        // ---- async bulk store smem -> gmem (TMA engine), one thread ----
        if (tid == 0) {
            asm volatile("fence.proxy.async.shared::cta;" ::: "memory");
            const uint32_t saddr = smem_u32(smb);
            float* gptr = out + (size_t)(ba * HW + p0) * ATTR;
            const uint32_t bytes = (uint32_t)(nvalid * ATTR * 4);  // 16B mult.
            asm volatile(
                "cp.async.bulk.global.shared::cta.bulk_group [%0], [%1], %2;"
                :: "l"(gptr), "r"(saddr), "r"(bytes) : "memory");
            asm volatile("cp.async.bulk.commit_group;" ::: "memory");
            // allow the just-issued store in flight; ensure the store that
            // used THIS buffer's partner (2 tiles ago) has drained
            asm volatile("cp.async.bulk.wait_group 1;" ::: "memory");
        }
        __syncthreads();   // broadcast: other buffer is safe to refill
    }

    // drain outstanding bulk stores before exit
    if (tid == 0)
        asm volatile("cp.async.bulk.wait_group 0;" ::: "memory");
}

extern "C" void kernel_launch(void* const* d_in, const int* in_sizes, int n_in,
                              void* d_out, int out_size) {
    const float* x = (const float*)d_in[0];
    float* out = (float*)d_out;
    yolo_kernel<<<NBLOCKS, NTHREADS>>>(x, out);
}